// round 17
// baseline (speedup 1.0000x reference)
#include <cuda_runtime.h>
#include <math.h>

#define BB 128
#define JJ 10
#define DD 16
#define II 6400
#define KK 8
#define CC 32
#define REP 200        // capsules per channel
#define GC  16         // channel-groups per batch (2 channels per block)

__device__ float g_Sx[BB * CC * KK];         // per-channel input sums
__device__ float g_V0[BB * 160];             // iter-0 outputs
__device__ float g_V1[BB * 160];             // V0 + iter-1 outputs
__device__ float g_part1[BB * GC * 160];     // iter-1 partial s
__device__ float g_part2[BB * GC * 160];     // iter-2 partial s

__device__ __forceinline__ void cp16(float* dst, const float* src) {
    unsigned sdst = (unsigned)__cvta_generic_to_shared(dst);
    asm volatile("cp.async.cg.shared.global [%0], [%1], 16;\n" :: "r"(sdst), "l"(src));
}
__device__ __forceinline__ void cp_commit() { asm volatile("cp.async.commit_group;\n"); }
__device__ __forceinline__ void cp_wait0()  { asm volatile("cp.async.wait_group 0;\n"); }

// ---- packed fp32 pair helpers (FFMA2 path, full fp32 precision) ----
__device__ __forceinline__ void fma2(unsigned long long& acc,
                                     unsigned long long a, unsigned long long b) {
    asm("fma.rn.f32x2 %0, %1, %2, %0;" : "+l"(acc) : "l"(a), "l"(b));
}
__device__ __forceinline__ unsigned long long bcast2(float c) {
    unsigned long long r; asm("mov.b64 %0, {%1, %1};" : "=l"(r) : "f"(c)); return r;
}
__device__ __forceinline__ float2 unpack2(unsigned long long v) {
    float2 f; asm("mov.b64 {%0, %1}, %2;" : "=f"(f.x), "=f"(f.y) : "l"(v)); return f;
}

// ---------------------------------------------------------------------------
// k_sum: Sx[b,c,k] = sum_{i in channel c} x[b,i,k].  grid (CC, BB), block 128.
// ---------------------------------------------------------------------------
__global__ __launch_bounds__(128) void k_sum(const float* __restrict__ x) {
    const int c = blockIdx.x, b = blockIdx.y, tid = threadIdx.x;
    const float4* xp = reinterpret_cast<const float4*>(
        x + ((size_t)b * II + (size_t)c * REP) * KK);   // 400 float4

    float4 a = make_float4(0.f, 0.f, 0.f, 0.f);
    for (int p = tid; p < 400; p += 128) {              // p%2 == tid%2 (fixed k-half)
        const float4 v = xp[p];
        a.x += v.x; a.y += v.y; a.z += v.z; a.w += v.w;
    }
#pragma unroll
    for (int m = 2; m <= 16; m <<= 1) {
        a.x += __shfl_xor_sync(0xffffffffu, a.x, m);
        a.y += __shfl_xor_sync(0xffffffffu, a.y, m);
        a.z += __shfl_xor_sync(0xffffffffu, a.z, m);
        a.w += __shfl_xor_sync(0xffffffffu, a.w, m);
    }
    __shared__ float sred[4][2][4];
    const int w = tid >> 5, l = tid & 31;
    if (l < 2) { sred[w][l][0] = a.x; sred[w][l][1] = a.y;
                 sred[w][l][2] = a.z; sred[w][l][3] = a.w; }
    __syncthreads();
    if (tid < KK) {
        float s = 0.f;
#pragma unroll
        for (int ww = 0; ww < 4; ++ww) s += sred[ww][tid >> 2][tid & 3];
        g_Sx[(b * CC + c) * KK + tid] = s;
    }
}

// ---------------------------------------------------------------------------
// k_v0: V0[b] = squash(0.1 * W·Sx[b] + B).  grid BB, block 256 (160 active).
// ---------------------------------------------------------------------------
__global__ __launch_bounds__(256) void k_v0(const float* __restrict__ W,
                                            const float* __restrict__ Bv) {
    const int b = blockIdx.x, tid = threadIdx.x;
    __shared__ float Ss[CC * KK];
    __shared__ float sv[160];
    __shared__ float fb[JJ];
    if (tid < CC * KK) Ss[tid] = g_Sx[b * CC * KK + tid];
    __syncthreads();
    if (tid < 160) {
        const int j = tid / DD, d = tid % DD;
        float acc = 0.f;
#pragma unroll 4
        for (int c = 0; c < CC; ++c) {
            const float4 w0 = *reinterpret_cast<const float4*>(
                W + (size_t)(j * CC + c) * 128 + d * 8);
            const float4 w1 = *reinterpret_cast<const float4*>(
                W + (size_t)(j * CC + c) * 128 + d * 8 + 4);
            const float4 s0 = *reinterpret_cast<const float4*>(Ss + c * 8);
            const float4 s1 = *reinterpret_cast<const float4*>(Ss + c * 8 + 4);
            acc = fmaf(w0.x, s0.x, acc); acc = fmaf(w0.y, s0.y, acc);
            acc = fmaf(w0.z, s0.z, acc); acc = fmaf(w0.w, s0.w, acc);
            acc = fmaf(w1.x, s1.x, acc); acc = fmaf(w1.y, s1.y, acc);
            acc = fmaf(w1.z, s1.z, acc); acc = fmaf(w1.w, s1.w, acc);
        }
        sv[tid] = 0.1f * acc + Bv[tid];
    }
    __syncthreads();
    if (tid < JJ) {
        float sq = 0.f;
#pragma unroll
        for (int d = 0; d < DD; ++d) { const float v = sv[tid * DD + d]; sq += v * v; }
        fb[tid] = sqrtf(sq) / (1.0f + sq);
    }
    __syncthreads();
    if (tid < 160) g_V0[b * 160 + tid] = sv[tid] * fb[tid / DD];
}

// ---------------------------------------------------------------------------
// k_route: one routing pass, TWO channels per block processed SEQUENTIALLY.
// grid (GC, BB), block 256.  FFMA2 inner loops; transposed coef matrix.
// ---------------------------------------------------------------------------
__global__ __launch_bounds__(256) void k_route(const float* __restrict__ x,
                                               const float* __restrict__ W,
                                               const float* __restrict__ Vsrc,
                                               float* __restrict__ dst) {
    __shared__ __align__(16) float xs[3200];   // [ch][i][k]  (both channels)
    __shared__ __align__(16) float Pq[160];    // [ch][j][k]
    __shared__ __align__(16) float cst[2000];  // [j][i]  transposed coefs (cur channel)
    __shared__ __align__(16) float part[800];  // [chunk*20+g][4], 10 chunks
    __shared__ __align__(16) float Tt[80];     // [j*8+k] (current channel)
    __shared__ __align__(16) float Vs[160];

    const int gc  = blockIdx.x;
    const int b   = blockIdx.y;
    const int tid = threadIdx.x;
    const int c0  = gc * 2;
    const float* xb = x + ((size_t)b * II + (size_t)c0 * REP) * KK;

    for (int t = tid; t < 800; t += 256) cp16(xs + t * 4, xb + t * 4);
    cp_commit();

    if (tid < 160) Vs[tid] = Vsrc[b * 160 + tid];
    __syncthreads();

    // P[ch,j,k] = sum_d Vs[j,d] * W[j,c0+ch,d,k]  (both channels up front)
    if (tid < 160) {
        const int ch = tid / 80, r = tid % 80, j = r >> 3, k = r & 7;
        const float* Wp = W + ((size_t)(j * CC + c0 + ch)) * 128 + k;
        float acc = 0.f;
#pragma unroll
        for (int d = 0; d < DD; ++d) acc = fmaf(Vs[j * DD + d], Wp[d * 8], acc);
        Pq[ch * 80 + j * 8 + k] = acc;
    }
    cp_wait0();
    __syncthreads();           // xs + Pq ready

    float sreg = 0.f;          // per-thread (tid<160) partial s accumulator

#pragma unroll
    for (int ch = 0; ch < 2; ++ch) {
        // ---- fused: phase D of ch0 on the ch1 pass ----
        if (ch == 1 && tid < 160) {
            const int j = tid / DD, d = tid % DD;
            const float4 w0 = *reinterpret_cast<const float4*>(
                W + (size_t)(j * CC + c0) * 128 + d * 8);
            const float4 w1 = *reinterpret_cast<const float4*>(
                W + (size_t)(j * CC + c0) * 128 + d * 8 + 4);
            const float4 t0 = *reinterpret_cast<const float4*>(Tt + j * 8);
            const float4 t1 = *reinterpret_cast<const float4*>(Tt + j * 8 + 4);
            sreg = fmaf(w0.x, t0.x, sreg); sreg = fmaf(w0.y, t0.y, sreg);
            sreg = fmaf(w0.z, t0.z, sreg); sreg = fmaf(w0.w, t0.w, sreg);
            sreg = fmaf(w1.x, t1.x, sreg); sreg = fmaf(w1.y, t1.y, sreg);
            sreg = fmaf(w1.z, t1.z, sreg); sreg = fmaf(w1.w, t1.w, sreg);
        }

        // ---- phase A: logits + softmax, FFMA2 (200 active) ----
        if (tid < REP) {
            const int i = tid;
            const ulonglong2* xq = reinterpret_cast<const ulonglong2*>(
                xs + ch * 1600 + i * 8);
            const ulonglong2 x0 = xq[0], x1 = xq[1];   // pairs (k0,k1)(k2,k3)(k4,k5)(k6,k7)
            float e[JJ], sum = 0.f;
#pragma unroll
            for (int j = 0; j < JJ; ++j) {
                const ulonglong2* pv = reinterpret_cast<const ulonglong2*>(
                    Pq + ch * 80 + j * 8);
                const ulonglong2 p0 = pv[0], p1 = pv[1];
                unsigned long long acc = 0ull;          // (0.0f, 0.0f)
                fma2(acc, x0.x, p0.x);
                fma2(acc, x0.y, p0.y);
                fma2(acc, x1.x, p1.x);
                fma2(acc, x1.y, p1.y);
                const float2 lv = unpack2(acc);
                // logits bounded (|V|<=2, |u_hat|<~4): exp safe without max-sub
                e[j] = __expf(lv.x + lv.y);
                sum += e[j];
            }
            const float r = __fdividef(1.0f, sum);
#pragma unroll
            for (int j = 0; j < JJ; ++j) cst[j * REP + i] = e[j] * r;
        }
        __syncthreads();

        // ---- phase B: partial T (10 chunks x 20 capsules, 200 threads) ----
        if (tid < 200) {
            const int chunk = tid / 20, g = tid % 20;
            const int j = g >> 1, kh = g & 1;
            const int i0 = chunk * 20;
            unsigned long long accA = 0ull, accB = 0ull;
            const float* cb = cst + j * REP + i0;
            const float* xpB = xs + ch * 1600 + i0 * 8 + kh * 4;
#pragma unroll
            for (int ii = 0; ii < 20; ii += 4) {
                const float4 cf = *reinterpret_cast<const float4*>(cb + ii);
                const ulonglong2 v0 = *reinterpret_cast<const ulonglong2*>(xpB + (ii + 0) * 8);
                const ulonglong2 v1 = *reinterpret_cast<const ulonglong2*>(xpB + (ii + 1) * 8);
                const ulonglong2 v2 = *reinterpret_cast<const ulonglong2*>(xpB + (ii + 2) * 8);
                const ulonglong2 v3 = *reinterpret_cast<const ulonglong2*>(xpB + (ii + 3) * 8);
                const unsigned long long c0p = bcast2(cf.x);
                const unsigned long long c1p = bcast2(cf.y);
                const unsigned long long c2p = bcast2(cf.z);
                const unsigned long long c3p = bcast2(cf.w);
                fma2(accA, c0p, v0.x); fma2(accB, c0p, v0.y);
                fma2(accA, c1p, v1.x); fma2(accB, c1p, v1.y);
                fma2(accA, c2p, v2.x); fma2(accB, c2p, v2.y);
                fma2(accA, c3p, v3.x); fma2(accB, c3p, v3.y);
            }
            const float2 a01 = unpack2(accA);
            const float2 a23 = unpack2(accB);
            *reinterpret_cast<float4*>(part + tid * 4) =
                make_float4(a01.x, a01.y, a23.x, a23.y);
        }
        __syncthreads();

        // ---- phase C: combine -> Tt ----
        if (tid < 80) {
            const int j = tid >> 3, k = tid & 7;
            const int g = j * 2 + (k >> 2), q = k & 3;
            float t = 0.f;
#pragma unroll
            for (int chunk = 0; chunk < 10; ++chunk)
                t += part[(chunk * 20 + g) * 4 + q];
            Tt[tid] = t;
        }
        __syncthreads();
    }

    // ---- final phase D (ch 1) + store ----
    if (tid < 160) {
        const int j = tid / DD, d = tid % DD;
        const float4 w0 = *reinterpret_cast<const float4*>(
            W + (size_t)(j * CC + c0 + 1) * 128 + d * 8);
        const float4 w1 = *reinterpret_cast<const float4*>(
            W + (size_t)(j * CC + c0 + 1) * 128 + d * 8 + 4);
        const float4 t0 = *reinterpret_cast<const float4*>(Tt + j * 8);
        const float4 t1 = *reinterpret_cast<const float4*>(Tt + j * 8 + 4);
        sreg = fmaf(w0.x, t0.x, sreg); sreg = fmaf(w0.y, t0.y, sreg);
        sreg = fmaf(w0.z, t0.z, sreg); sreg = fmaf(w0.w, t0.w, sreg);
        sreg = fmaf(w1.x, t1.x, sreg); sreg = fmaf(w1.y, t1.y, sreg);
        sreg = fmaf(w1.z, t1.z, sreg); sreg = fmaf(w1.w, t1.w, sreg);
        dst[((size_t)b * GC + gc) * 160 + tid] = sreg;
    }
}

// ---------------------------------------------------------------------------
// k_v1: V1[b] = V0[b] + squash(sum_gc g_part1[b] + B).  grid BB, block 160.
// ---------------------------------------------------------------------------
__global__ __launch_bounds__(160) void k_v1(const float* __restrict__ Bv) {
    const int b = blockIdx.x, tid = threadIdx.x;
    __shared__ float sv[160];
    __shared__ float fb[JJ];
    const float* src = g_part1 + (size_t)b * GC * 160;
    float s = Bv[tid];
#pragma unroll 8
    for (int g2 = 0; g2 < GC; ++g2) s += src[g2 * 160 + tid];
    sv[tid] = s;
    __syncthreads();
    if (tid < JJ) {
        float sq = 0.f;
#pragma unroll
        for (int d = 0; d < DD; ++d) { const float v = sv[tid * DD + d]; sq += v * v; }
        fb[tid] = sqrtf(sq) / (1.0f + sq);
    }
    __syncthreads();
    g_V1[b * 160 + tid] = g_V0[b * 160 + tid] + sv[tid] * fb[tid / DD];
}

// ---------------------------------------------------------------------------
// k_final: out[b] = squash(sum_gc g_part2[b] + B).  grid BB, block 160.
// ---------------------------------------------------------------------------
__global__ __launch_bounds__(160) void k_final(const float* __restrict__ Bv,
                                               float* __restrict__ out) {
    const int b = blockIdx.x, tid = threadIdx.x;
    __shared__ float sv[160];
    __shared__ float fb[JJ];
    const float* src = g_part2 + (size_t)b * GC * 160;
    float s = Bv[tid];
#pragma unroll 8
    for (int g2 = 0; g2 < GC; ++g2) s += src[g2 * 160 + tid];
    sv[tid] = s;
    __syncthreads();
    if (tid < JJ) {
        float sq = 0.f;
#pragma unroll
        for (int d = 0; d < DD; ++d) { const float v = sv[tid * DD + d]; sq += v * v; }
        fb[tid] = sqrtf(sq) / (1.0f + sq);
    }
    __syncthreads();
    out[(size_t)b * 160 + tid] = sv[tid] * fb[tid / DD];
}

// ---------------------------------------------------------------------------
extern "C" void kernel_launch(void* const* d_in, const int* in_sizes, int n_in,
                              void* d_out, int out_size) {
    const float* x  = (const float*)d_in[0];  // [128, 6400, 8]
    const float* W  = (const float*)d_in[1];  // [10, 32, 16, 8]
    const float* Bv = (const float*)d_in[2];  // [10, 16]
    float* out = (float*)d_out;               // [128, 10, 16]

    float *pV0, *pV1, *pP1, *pP2;
    cudaGetSymbolAddress((void**)&pV0, g_V0);
    cudaGetSymbolAddress((void**)&pV1, g_V1);
    cudaGetSymbolAddress((void**)&pP1, g_part1);
    cudaGetSymbolAddress((void**)&pP2, g_part2);

    const dim3 gr(GC, BB);
    k_sum<<<dim3(CC, BB), 128>>>(x);
    k_v0<<<BB, 256>>>(W, Bv);
    k_route<<<gr, 256>>>(x, W, pV0, pP1);    // iter 1
    k_v1<<<BB, 160>>>(Bv);
    k_route<<<gr, 256>>>(x, W, pV1, pP2);    // iter 2
    k_final<<<BB, 160>>>(Bv, out);
}